// round 1
// baseline (speedup 1.0000x reference)
#include <cuda_runtime.h>
#include <cstdint>

// ReprojectionLayer: out[b,j,x,y,z] = mean_c heatmaps[b,c,j, v*512+u]
//   where (u,v) = reproLookup[c, sx+x, sy+y, sz+z, :], s* = clamp(trunc((center-OFFSET)/SPACING)-52, 0, L-G)
//
// Inputs (metadata order):
//   d_in[0] heatmaps   float32 [2,12,23,512,512]
//   d_in[1] center     float32 [2,3]
//   d_in[2] reproLookup int32  [12,160,160,160,2]
// Output: float32 [2,23,104,104,104]

#define NB 2
#define NC 12
#define NJ 23
#define GG 104
#define HALFG 52
#define LL 160
#define HMW 512
#define HW (512 * 512)
#define G3 (GG * GG * GG)

__global__ __launch_bounds__(256) void repro_kernel(
    const float* __restrict__ heatmaps,
    const float* __restrict__ center,
    const int2* __restrict__ lookup,
    float* __restrict__ out)
{
    const int b = blockIdx.y;
    const int vox = blockIdx.x * blockDim.x + threadIdx.x;
    if (vox >= G3) return;

    // voxel coords: vox = (x*G + y)*G + z  (z fastest)
    const int z = vox % GG;
    const int t = vox / GG;
    const int y = t % GG;
    const int x = t / GG;

    // center indices: trunc((center - OFFSET)/SPACING) - HALF, clamped like dynamic_slice
    int sx = (int)((center[b * 3 + 0] + 160.0f) * 0.5f) - HALFG;
    int sy = (int)((center[b * 3 + 1] + 160.0f) * 0.5f) - HALFG;
    int sz = (int)((center[b * 3 + 2] + 160.0f) * 0.5f) - HALFG;
    sx = min(max(sx, 0), LL - GG);
    sy = min(max(sy, 0), LL - GG);
    sz = min(max(sz, 0), LL - GG);

    const int lx = sx + x, ly = sy + y, lz = sz + z;

    // Precompute per-cam combined offset: c*(J*HW) + flat[c]
    // (max = 11*23*262144 + 262143 < 2^31, safe in int)
    int off[NC];
#pragma unroll
    for (int c = 0; c < NC; ++c) {
        const int lidx = ((c * LL + lx) * LL + ly) * LL + lz;
        const int2 uv = __ldg(&lookup[lidx]);
        off[c] = c * (NJ * HW) + (uv.y * HMW + uv.x);
    }

    const float* hmb = heatmaps + (size_t)b * (NC * NJ) * HW;
    float* outb = out + ((size_t)b * NJ) * G3 + vox;

#pragma unroll 1
    for (int j = 0; j < NJ; ++j) {
        const float* hmj = hmb + j * HW;
        float a = 0.0f;
#pragma unroll
        for (int c = 0; c < NC; ++c)
            a += __ldg(hmj + off[c]);
        outb[(size_t)j * G3] = a * (1.0f / 12.0f);
    }
}

extern "C" void kernel_launch(void* const* d_in, const int* in_sizes, int n_in,
                              void* d_out, int out_size)
{
    const float* heatmaps = (const float*)d_in[0];
    const float* center   = (const float*)d_in[1];
    const int2*  lookup   = (const int2*)d_in[2];
    float* out = (float*)d_out;

    dim3 block(256);
    dim3 grid((G3 + 255) / 256, NB);
    repro_kernel<<<grid, block>>>(heatmaps, center, lookup, out);
}

// round 3
// speedup vs baseline: 8.3289x; 8.3289x over previous
#include <cuda_runtime.h>
#include <cstdint>

// ReprojectionLayer: out[b,j,x,y,z] = mean_c heatmaps[b,c,j, v*512+u]
//   (u,v) = reproLookup[c, sx+x, sy+y, sz+z, :], s* = clamp(trunc((center+160)/2)-52, 0, L-G)
//
// Strategy:
//   Pass 1: transpose heatmaps [B,C,J,HW] -> T[B,C,HW,24] (j innermost, padded to 24)
//           so the 23 joint values for one (u,v) are 96 contiguous bytes (3 sectors,
//           6 aligned float4) instead of 23 sectors at 1MB stride.
//   Pass 2: per (b,voxel): 12 lookup reads -> 12*6 float4 gathers -> 23 accumulators
//           -> 23 coalesced writes.

#define NB 2
#define NC 12
#define NJ 23
#define NJP 24          // padded joints (96B rows, float4-aligned)
#define GG 104
#define HALFG 52
#define LL 160
#define HMW 512
#define HW (512 * 512)
#define G3 (GG * GG * GG)   // 1,124,864 (divisible by 256)

// Scratch: 2*12*262144 rows * 6 float4 = 604 MB
__device__ float4 g_T[(size_t)NB * NC * HW * (NJP / 4)];

// ---------------- Pass 1: transpose ----------------
// grid = (HW/256, NC, NB), block = 256. Each block handles 256 pixels of one (b,c).
__global__ __launch_bounds__(256) void transpose_kernel(const float* __restrict__ hm)
{
    __shared__ float s[256 * 25];   // stride 25 to avoid bank conflicts on store
    const int c = blockIdx.y, b = blockIdx.z;
    const int p0 = blockIdx.x * 256;
    const int tid = threadIdx.x;

    const float* src = hm + ((size_t)(b * NC + c) * NJ) * HW + p0 + tid;
#pragma unroll
    for (int j = 0; j < NJ; ++j)
        s[tid * 25 + j] = src[(size_t)j * HW];      // coalesced across lanes
    s[tid * 25 + 23] = 0.0f;                        // pad
    __syncthreads();

    // write 256 rows * 6 float4, fully contiguous
    float4* dst = g_T + ((size_t)(b * NC + c) * HW + p0) * (NJP / 4);
#pragma unroll
    for (int i = tid; i < 256 * 6; i += 256) {
        const int pl = i / 6, part = i % 6;
        const float* sp = s + pl * 25 + part * 4;
        dst[i] = make_float4(sp[0], sp[1], sp[2], sp[3]);
    }
}

// ---------------- Pass 2: gather + mean ----------------
__global__ __launch_bounds__(256) void gather_kernel(
    const float* __restrict__ center,
    const int2* __restrict__ lookup,
    float* __restrict__ out)
{
    const int b = blockIdx.y;
    const int vox = blockIdx.x * blockDim.x + threadIdx.x;
    if (vox >= G3) return;

    const int z = vox % GG;
    const int t = vox / GG;
    const int y = t % GG;
    const int x = t / GG;

    int sx = (int)((center[b * 3 + 0] + 160.0f) * 0.5f) - HALFG;
    int sy = (int)((center[b * 3 + 1] + 160.0f) * 0.5f) - HALFG;
    int sz = (int)((center[b * 3 + 2] + 160.0f) * 0.5f) - HALFG;
    sx = min(max(sx, 0), LL - GG);
    sy = min(max(sy, 0), LL - GG);
    sz = min(max(sz, 0), LL - GG);

    const int lx = sx + x, ly = sy + y, lz = sz + z;

    // 12 coalesced lookup reads -> float4-row bases in g_T
    int base6[NC];
#pragma unroll
    for (int c = 0; c < NC; ++c) {
        const int lidx = ((c * LL + lx) * LL + ly) * LL + lz;
        const int2 uv = __ldg(&lookup[lidx]);
        base6[c] = ((b * NC + c) * HW + (uv.y * HMW + uv.x)) * (NJP / 4);
    }

    float acc[NJP];
#pragma unroll
    for (int j = 0; j < NJP; ++j) acc[j] = 0.0f;

#pragma unroll
    for (int c = 0; c < NC; ++c) {
        const float4* row = g_T + base6[c];
#pragma unroll
        for (int part = 0; part < 6; ++part) {
            const float4 q = __ldg(row + part);
            acc[part * 4 + 0] += q.x;
            acc[part * 4 + 1] += q.y;
            acc[part * 4 + 2] += q.z;
            acc[part * 4 + 3] += q.w;
        }
    }

    float* outb = out + ((size_t)b * NJ) * G3 + vox;
#pragma unroll
    for (int j = 0; j < NJ; ++j)
        outb[(size_t)j * G3] = acc[j] * (1.0f / 12.0f);
}

extern "C" void kernel_launch(void* const* d_in, const int* in_sizes, int n_in,
                              void* d_out, int out_size)
{
    const float* heatmaps = (const float*)d_in[0];
    const float* center   = (const float*)d_in[1];
    const int2*  lookup   = (const int2*)d_in[2];
    float* out = (float*)d_out;

    {
        dim3 grid(HW / 256, NC, NB);
        transpose_kernel<<<grid, 256>>>(heatmaps);
    }
    {
        dim3 grid(G3 / 256, NB);
        gather_kernel<<<grid, 256>>>(center, lookup, out);
    }
}

// round 6
// speedup vs baseline: 13.3517x; 1.6031x over previous
#include <cuda_runtime.h>
#include <cuda_fp16.h>
#include <cstdint>

// ReprojectionLayer: out[b,j,x,y,z] = mean_c heatmaps[b,c,j, v*512+u]
//   (u,v) = reproLookup[c, sx+x, sy+y, sz+z, :], s* = clamp(trunc((center+160)/2)-52, 0, L-G)
//
// Strategy:
//   Pass 1: transpose+convert heatmaps [B,C,J,HW] fp32 -> T[B,C,HW,24] fp16
//           (j innermost, padded 23->24). One (u,v) row = 48B = exactly 2 sectors,
//           three aligned 16B loads.
//   Pass 2: per (b,voxel): 12 lookup reads -> 12*3 uint4 gathers (fp16) -> fp32
//           accumulate 23 joints -> coalesced writes.
// Precision: values in [0,1); fp16 rel err <= 2^-11 < 1e-3 threshold; fp32 accum.

#define NB 2
#define NC 12
#define NJ 23
#define NJP 24          // padded joints: 24 halves = 48B rows
#define GG 104
#define HALFG 52
#define LL 160
#define HMW 512
#define HW (512 * 512)
#define G3 (GG * GG * GG)   // 1,124,864 (divisible by 256)

__device__ __forceinline__ uint32_t h2_to_u32(__half2 h) {
    return *reinterpret_cast<uint32_t*>(&h);
}
__device__ __forceinline__ __half2 u32_to_h2(uint32_t u) {
    return *reinterpret_cast<__half2*>(&u);
}

// Scratch: 2*12*262144 rows * 3 uint4 (48B) = 302 MB
__device__ uint4 g_T[(size_t)NB * NC * HW * 3];

// ---------------- Pass 1: transpose + fp32->fp16 ----------------
// grid = (HW/256, NC, NB), block = 256. Each block: 256 pixels of one (b,c).
__global__ __launch_bounds__(256) void transpose_kernel(const float* __restrict__ hm)
{
    __shared__ float s[256 * 25];   // stride 25: odd word stride, conflict-free col access
    const int c = blockIdx.y, b = blockIdx.z;
    const int p0 = blockIdx.x * 256;
    const int tid = threadIdx.x;

    const float* src = hm + ((size_t)(b * NC + c) * NJ) * HW + p0 + tid;
#pragma unroll
    for (int j = 0; j < NJ; ++j)
        s[tid * 25 + j] = src[(size_t)j * HW];      // coalesced across lanes
    s[tid * 25 + 23] = 0.0f;                        // pad joint
    __syncthreads();

    // write 256 rows * 3 uint4 (8 halves each), fully contiguous
    uint4* dst = g_T + ((size_t)(b * NC + c) * HW + p0) * 3;
#pragma unroll
    for (int i = tid; i < 256 * 3; i += 256) {
        const int pl = i / 3, part = i % 3;
        const float* sp = s + pl * 25 + part * 8;
        uint4 v;
        v.x = h2_to_u32(__floats2half2_rn(sp[0], sp[1]));
        v.y = h2_to_u32(__floats2half2_rn(sp[2], sp[3]));
        v.z = h2_to_u32(__floats2half2_rn(sp[4], sp[5]));
        v.w = h2_to_u32(__floats2half2_rn(sp[6], sp[7]));
        dst[i] = v;
    }
}

// ---------------- Pass 2: gather + mean ----------------
__global__ __launch_bounds__(256) void gather_kernel(
    const float* __restrict__ center,
    const int2* __restrict__ lookup,
    float* __restrict__ out)
{
    const int b = blockIdx.y;
    const int vox = blockIdx.x * blockDim.x + threadIdx.x;
    if (vox >= G3) return;

    const int z = vox % GG;
    const int t = vox / GG;
    const int y = t % GG;
    const int x = t / GG;

    int sx = (int)((center[b * 3 + 0] + 160.0f) * 0.5f) - HALFG;
    int sy = (int)((center[b * 3 + 1] + 160.0f) * 0.5f) - HALFG;
    int sz = (int)((center[b * 3 + 2] + 160.0f) * 0.5f) - HALFG;
    sx = min(max(sx, 0), LL - GG);
    sy = min(max(sy, 0), LL - GG);
    sz = min(max(sz, 0), LL - GG);

    const int lx = sx + x, ly = sy + y, lz = sz + z;

    // 12 coalesced lookup reads -> uint4-row bases in g_T
    int base3[NC];
#pragma unroll
    for (int c = 0; c < NC; ++c) {
        const int lidx = ((c * LL + lx) * LL + ly) * LL + lz;
        const int2 uv = __ldg(&lookup[lidx]);
        base3[c] = ((b * NC + c) * HW + (uv.y * HMW + uv.x)) * 3;
    }

    float acc[NJP];
#pragma unroll
    for (int j = 0; j < NJP; ++j) acc[j] = 0.0f;

#pragma unroll
    for (int c = 0; c < NC; ++c) {
        const uint4* row = g_T + base3[c];
#pragma unroll
        for (int part = 0; part < 3; ++part) {
            const uint4 q = __ldg(row + part);
            const float2 f0 = __half22float2(u32_to_h2(q.x));
            const float2 f1 = __half22float2(u32_to_h2(q.y));
            const float2 f2 = __half22float2(u32_to_h2(q.z));
            const float2 f3 = __half22float2(u32_to_h2(q.w));
            float* a = acc + part * 8;
            a[0] += f0.x; a[1] += f0.y;
            a[2] += f1.x; a[3] += f1.y;
            a[4] += f2.x; a[5] += f2.y;
            a[6] += f3.x; a[7] += f3.y;
        }
    }

    float* outb = out + ((size_t)b * NJ) * G3 + vox;
#pragma unroll
    for (int j = 0; j < NJ; ++j)
        outb[(size_t)j * G3] = acc[j] * (1.0f / 12.0f);
}

extern "C" void kernel_launch(void* const* d_in, const int* in_sizes, int n_in,
                              void* d_out, int out_size)
{
    const float* heatmaps = (const float*)d_in[0];
    const float* center   = (const float*)d_in[1];
    const int2*  lookup   = (const int2*)d_in[2];
    float* out = (float*)d_out;

    {
        dim3 grid(HW / 256, NC, NB);
        transpose_kernel<<<grid, 256>>>(heatmaps);
    }
    {
        dim3 grid(G3 / 256, NB);
        gather_kernel<<<grid, 256>>>(center, lookup, out);
    }
}